// round 15
// baseline (speedup 1.0000x reference)
#include <cuda_runtime.h>
#include <cuda_fp16.h>
#include <cstdint>
#include <math.h>

#define B_  2
#define S_  2048
#define D_  2048
#define H_  16
#define HD_ 128
#define M_  (B_ * S_)
#define BS_D (B_ * S_ * D_)
#define WSZ (D_ * D_)
#define LOG2E 1.4426950408889634f

// Scratch (device globals — no allocation allowed)
__device__ __align__(16) __half g_xh[BS_D];
__device__ __align__(16) __half g_wh[4 * WSZ];
__device__ __align__(16) __half g_q[BS_D], g_k[BS_D], g_v[BS_D];
__device__ __align__(16) __half g_ch[BS_D];

// ===================== helpers =====================
__device__ __forceinline__ void cp16(uint32_t dst, const void* src) {
    asm volatile("cp.async.cg.shared.global [%0], [%1], 16;"
                 :: "r"(dst), "l"(src) : "memory");
}
#define CP_COMMIT() asm volatile("cp.async.commit_group;" ::: "memory")
#define CP_WAIT0()  asm volatile("cp.async.wait_group 0;" ::: "memory")
#define CP_WAIT1()  asm volatile("cp.async.wait_group 1;" ::: "memory")

__device__ __forceinline__ void ldm_x4(uint32_t* r, uint32_t addr) {
    asm volatile("ldmatrix.sync.aligned.m8n8.x4.shared.b16 {%0,%1,%2,%3}, [%4];"
                 : "=r"(r[0]), "=r"(r[1]), "=r"(r[2]), "=r"(r[3]) : "r"(addr));
}
__device__ __forceinline__ void ldm_x4t(uint32_t* r, uint32_t addr) {
    asm volatile("ldmatrix.sync.aligned.m8n8.x4.trans.shared.b16 {%0,%1,%2,%3}, [%4];"
                 : "=r"(r[0]), "=r"(r[1]), "=r"(r[2]), "=r"(r[3]) : "r"(addr));
}

// fp16 m16n8k16, fp32 accumulate
__device__ __forceinline__ void mma16(float* d, const uint32_t* a, const uint32_t* b) {
    asm volatile("mma.sync.aligned.m16n8k16.row.col.f32.f16.f16.f32 "
                 "{%0,%1,%2,%3}, {%4,%5,%6,%7}, {%8,%9}, {%0,%1,%2,%3};"
                 : "+f"(d[0]), "+f"(d[1]), "+f"(d[2]), "+f"(d[3])
                 : "r"(a[0]), "r"(a[1]), "r"(a[2]), "r"(a[3]),
                   "r"(b[0]), "r"(b[1]));
}

// fast exp2 on FMA pipe
__device__ __forceinline__ float exp2f_fast(float z) {
    z = fmaxf(z, -126.f);
    float r = z + 12582912.f;
    int   n = __float_as_int(r);
    float f = z - (r - 12582912.f);
    float p = 1.3333558146e-3f;
    p = fmaf(p, f, 9.6180216e-3f);
    p = fmaf(p, f, 5.5504109e-2f);
    p = fmaf(p, f, 2.4022651e-1f);
    p = fmaf(p, f, 6.9314718e-1f);
    p = fmaf(p, f, 1.0f);
    return __int_as_float(__float_as_int(p) + (n << 23));
}

// ===================== fused prepass: fp16 round (x + 4 W) =====================
#define N4X (BS_D / 4)
#define N4W (WSZ / 4)
__global__ __launch_bounds__(256) void split_all(
    const float* __restrict__ x,  const float* __restrict__ Wq,
    const float* __restrict__ Wk, const float* __restrict__ Wv,
    const float* __restrict__ Wo)
{
    int i = blockIdx.x * 256 + threadIdx.x;
    const float* src;
    __half* dst;
    int j;
    if (i < N4X) { src = x; dst = g_xh; j = i; }
    else {
        int w = (i - N4X) / N4W;
        j = (i - N4X) - w * N4W;
        src = (w == 0) ? Wq : (w == 1) ? Wk : (w == 2) ? Wv : Wo;
        dst = g_wh + w * WSZ;
    }
    float4 v = ((const float4*)src)[j];
    __half2 hp0 = {__float2half_rn(v.x), __float2half_rn(v.y)};
    __half2 hp1 = {__float2half_rn(v.z), __float2half_rn(v.w)};
    ((__half2*)dst)[2 * j]     = hp0;
    ((__half2*)dst)[2 * j + 1] = hp1;
}

// ===================== fp16 GEMM: k64 chunks, 3-stage, XOR-swizzled =====================
// tile = 128 rows x 64 fp16 (128B rows), swizzle g^(r&7) at 16B granules
#define GB_TILEB  16384
#define GB_STAGEB 32768
#define GB_NSTG   3
#define GB_NCH    (D_ / 64)              // 32 chunks
#define GB_SMEM   (GB_NSTG * GB_STAGEB + 512)   // 98816 B -> 2 CTAs/SM

__device__ __forceinline__ uint32_t swz64(int r, int g) {
    return (uint32_t)(r * 128 + (((g) ^ (r & 7)) << 4));
}

struct GemmJob { const __half *Ah, *Bh; const float* bias;
                 float* Cf; __half* Ch; float scale; };

__device__ __forceinline__ void g_issue64(const GemmJob& jb, int row0, int col0,
                                          int ch, uint32_t sbase, int tid) {
    const uint32_t st = sbase + (uint32_t)((ch % GB_NSTG) * GB_STAGEB);
    const int k0 = ch * 64;
#pragma unroll
    for (int j = 0; j < 4; j++) {
        int id = tid + 256 * j;          // 0..1023
        int r = id >> 3, g = id & 7;
        cp16(st + swz64(r, g),            jb.Ah + (size_t)(row0 + r) * D_ + k0 + g * 8);
        cp16(st + GB_TILEB + swz64(r, g), jb.Bh + (size_t)(col0 + r) * D_ + k0 + g * 8);
    }
}

__device__ __forceinline__ void gemm_body(const GemmJob& jb, int bx, int by)
{
    extern __shared__ uint32_t smw[];
    float* bias_s = (float*)(smw + GB_NSTG * GB_STAGEB / 4);
    const int tid = threadIdx.x, lane = tid & 31, wid = tid >> 5;
    const int row0 = by * 128, col0 = bx * 128;
    const uint32_t sbase = (uint32_t)__cvta_generic_to_shared(smw);
    const int m0w = (wid >> 2) * 64, n0w = (wid & 3) * 32;

    if (tid < 128) bias_s[tid] = jb.bias[col0 + tid];

    float acc[4][4][4];
#pragma unroll
    for (int a = 0; a < 4; a++)
#pragma unroll
        for (int b = 0; b < 4; b++)
#pragma unroll
            for (int c = 0; c < 4; c++) acc[a][b][c] = 0.f;

    g_issue64(jb, row0, col0, 0, sbase, tid); CP_COMMIT();
    g_issue64(jb, row0, col0, 1, sbase, tid); CP_COMMIT();

    const int lq  = lane >> 3;
    const int lr  = lane & 7;
    const int aRow = (lq & 1) * 8 + lr;
    const int aG   = lq >> 1;
    const int bRow = (lq >> 1) * 8 + lr;
    const int bG   = lq & 1;

    for (int ch = 0; ch < GB_NCH; ch++) {
        CP_WAIT1();
        __syncthreads();
        if (ch + 2 < GB_NCH) g_issue64(jb, row0, col0, ch + 2, sbase, tid);
        CP_COMMIT();

        const uint32_t stg = sbase + (uint32_t)((ch % GB_NSTG) * GB_STAGEB);
        const uint32_t sAh = stg;
        const uint32_t sBh = stg + GB_TILEB;

#pragma unroll
        for (int ks = 0; ks < 4; ks++) {
            const int gA = ks * 2 + aG;
            const int gB = ks * 2 + bG;
            uint32_t ah[4][4], bh[4][2];
#pragma unroll
            for (int mt = 0; mt < 4; mt++)
                ldm_x4(ah[mt], sAh + swz64(m0w + mt * 16 + aRow, gA));
#pragma unroll
            for (int np = 0; np < 2; np++) {
                uint32_t t[4];
                ldm_x4(t, sBh + swz64(n0w + np * 16 + bRow, gB));
                bh[np*2][0] = t[0]; bh[np*2][1] = t[1];
                bh[np*2+1][0] = t[2]; bh[np*2+1][1] = t[3];
            }
#pragma unroll
            for (int mt = 0; mt < 4; mt++)
#pragma unroll
                for (int nt = 0; nt < 4; nt++)
                    mma16(acc[mt][nt], ah[mt], bh[nt]);
        }
    }

#pragma unroll
    for (int mt = 0; mt < 4; mt++) {
        const int r = row0 + m0w + mt * 16 + (lane >> 2);
#pragma unroll
        for (int nt = 0; nt < 4; nt++) {
            const int cc = n0w + nt * 8 + 2 * (lane & 3);
            float v0 = (acc[mt][nt][0] + bias_s[cc]) * jb.scale;
            float v1 = (acc[mt][nt][1] + bias_s[cc + 1]) * jb.scale;
            float v2 = (acc[mt][nt][2] + bias_s[cc]) * jb.scale;
            float v3 = (acc[mt][nt][3] + bias_s[cc + 1]) * jb.scale;
            if (jb.Ch) {
                __half2 p0 = {__float2half_rn(v0), __float2half_rn(v1)};
                __half2 p1 = {__float2half_rn(v2), __float2half_rn(v3)};
                *(__half2*)&jb.Ch[(size_t)r * D_ + col0 + cc] = p0;
                *(__half2*)&jb.Ch[(size_t)(r + 8) * D_ + col0 + cc] = p1;
            } else {
                *(float2*)&jb.Cf[(size_t)r * D_ + col0 + cc] = make_float2(v0, v1);
                *(float2*)&jb.Cf[(size_t)(r + 8) * D_ + col0 + cc] = make_float2(v2, v3);
            }
        }
    }
}

__global__ __launch_bounds__(256, 2) void gemm_qkv(
    const float* __restrict__ bq, const float* __restrict__ bk,
    const float* __restrict__ bv, float qscale)
{
    GemmJob jb;
    const int z = blockIdx.z;
    jb.Ah = g_xh;
    jb.Bh = g_wh + z * WSZ;
    jb.bias = (z == 0) ? bq : (z == 1) ? bk : bv;
    jb.Cf = nullptr;
    jb.Ch = (z == 0) ? g_q : (z == 1) ? g_k : g_v;
    jb.scale = (z == 0) ? qscale : 1.f;
    gemm_body(jb, blockIdx.x, blockIdx.y);
}

__global__ __launch_bounds__(256, 2) void gemm_out(
    const float* __restrict__ bo, float* __restrict__ out)
{
    GemmJob jb;
    jb.Ah = g_ch;
    jb.Bh = g_wh + 3 * WSZ;
    jb.bias = bo; jb.Cf = out; jb.Ch = nullptr; jb.scale = 1.f;
    gemm_body(jb, blockIdx.x, blockIdx.y);
}

// ===================== fp16 mma flash attention (as R13) =====================
#define QB  0
#define KB  32768
#define VB  65536
#define PB  131072
#define MRF 36864
#define LRF 36992
#define SRF 37120
#define ATTN_SMEM 148992

#define SWZH(r, g) ((uint32_t)((r) * 256 + ((((g) ^ ((r) & 7))) << 4)))
#define SWZPG(r, g) ((uint32_t)((r) * 128 + ((((g) ^ ((r) & 7))) << 4)))
#define SFI(r, c) (24576 + (r) * 64 + ((c) ^ (((r) & 7) << 2)))

__global__ __launch_bounds__(256) void attn_tc()
{
    extern __shared__ float sm[];
    const int tid = threadIdx.x, lane = tid & 31, wid = tid >> 5;
    const int wR = wid >> 1, wC = wid & 1;
    const int q0 = ((int)gridDim.x - 1 - (int)blockIdx.x) * 128;
    const int h = blockIdx.y, b = blockIdx.z;
    const uint32_t sbase = (uint32_t)__cvta_generic_to_shared(sm);
    const size_t gbase = (size_t)b * S_ * D_ + (size_t)h * HD_;

    if (tid < 128) { sm[MRF + tid] = -1e30f; sm[LRF + tid] = 0.f; }

#pragma unroll
    for (int j = 0; j < 8; j++) {
        int id = tid + 256 * j, r = id >> 4, g = id & 15;
        cp16(sbase + QB + SWZH(r, g), &g_q[gbase + (size_t)(q0 + r) * D_ + g * 8]);
    }
#pragma unroll
    for (int j = 0; j < 4; j++) {
        int id = tid + 256 * j, r = id >> 4, g = id & 15;
        cp16(sbase + KB + SWZH(r, g), &g_k[gbase + (size_t)r * D_ + g * 8]);
        cp16(sbase + VB + SWZH(r, g), &g_v[gbase + (size_t)r * D_ + g * 8]);
    }
    CP_COMMIT();

    const int lq = lane >> 3, lr = lane & 7;
    const int aRow = (lq & 1) * 8 + lr;
    const int aG   = lq >> 1;
    const int bRow = (lq >> 1) * 8 + lr;
    const int bG   = lq & 1;

    float oacc[2][8][4];
#pragma unroll
    for (int a = 0; a < 2; a++)
#pragma unroll
        for (int c = 0; c < 8; c++)
#pragma unroll
            for (int e = 0; e < 4; e++) oacc[a][c][e] = 0.f;

    const int ntiles = q0 / 64 + 2;
    for (int t = 0; t < ntiles; t++) {
        const int s = t & 1;
        const int kv0 = t * 64;
        CP_WAIT0();
        __syncthreads();
        if (t + 1 < ntiles) {
            const size_t kr = gbase + (size_t)(kv0 + 64) * D_;
            const uint32_t so = (uint32_t)((s ^ 1) * 16384);
#pragma unroll
            for (int j = 0; j < 4; j++) {
                int id = tid + 256 * j, r = id >> 4, g = id & 15;
                cp16(sbase + KB + so + SWZH(r, g), &g_k[kr + (size_t)r * D_ + g * 8]);
                cp16(sbase + VB + so + SWZH(r, g), &g_v[kr + (size_t)r * D_ + g * 8]);
            }
            CP_COMMIT();
        }
        const uint32_t Kst = sbase + KB + (uint32_t)(s * 16384);
        const uint32_t Vst = sbase + VB + (uint32_t)(s * 16384);

        float sacc[2][4][4];
#pragma unroll
        for (int a = 0; a < 2; a++)
#pragma unroll
            for (int c = 0; c < 4; c++)
#pragma unroll
                for (int e = 0; e < 4; e++) sacc[a][c][e] = 0.f;

#pragma unroll
        for (int ks = 0; ks < 8; ks++) {
            uint32_t aq[2][4], bk[4][2];
#pragma unroll
            for (int mt = 0; mt < 2; mt++)
                ldm_x4(aq[mt], sbase + QB + SWZH(wR * 32 + mt * 16 + aRow, ks * 2 + aG));
#pragma unroll
            for (int np = 0; np < 2; np++) {
                uint32_t t4[4];
                ldm_x4(t4, Kst + SWZH(wC * 32 + np * 16 + bRow, ks * 2 + bG));
                bk[np*2][0] = t4[0]; bk[np*2][1] = t4[1];
                bk[np*2+1][0] = t4[2]; bk[np*2+1][1] = t4[3];
            }
#pragma unroll
            for (int mt = 0; mt < 2; mt++)
#pragma unroll
                for (int nt = 0; nt < 4; nt++)
                    mma16(sacc[mt][nt], aq[mt], bk[nt]);
        }

#pragma unroll
        for (int mt = 0; mt < 2; mt++) {
            const int rl = wR * 32 + mt * 16 + (lane >> 2);
#pragma unroll
            for (int nt = 0; nt < 4; nt++) {
                const int cl_ = wC * 32 + nt * 8 + 2 * (lane & 3);
                float e0 = (kv0 + cl_     <= q0 + rl)     ? sacc[mt][nt][0] : -1e30f;
                float e1 = (kv0 + cl_ + 1 <= q0 + rl)     ? sacc[mt][nt][1] : -1e30f;
                float e2 = (kv0 + cl_     <= q0 + rl + 8) ? sacc[mt][nt][2] : -1e30f;
                float e3 = (kv0 + cl_ + 1 <= q0 + rl + 8) ? sacc[mt][nt][3] : -1e30f;
                *(float2*)&sm[SFI(rl, cl_)]     = make_float2(e0, e1);
                *(float2*)&sm[SFI(rl + 8, cl_)] = make_float2(e2, e3);
            }
        }
        __syncthreads();

        {
            const int r = tid >> 1, cb = (tid & 1) * 32;
            float mx = -1e30f;
#pragma unroll
            for (int i = 0; i < 8; i++) {
                float4 v = *(const float4*)&sm[SFI(r, cb + i * 4)];
                mx = fmaxf(mx, fmaxf(fmaxf(v.x, v.y), fmaxf(v.z, v.w)));
            }
            mx = fmaxf(mx, __shfl_xor_sync(0xffffffffu, mx, 1));
            const float mold = sm[MRF + r];
            const float mnew = fmaxf(mold, mx);
            const float msl  = mnew * LOG2E;
            float sum = 0.f;
            char* smb = (char*)sm;
#pragma unroll
            for (int i = 0; i < 8; i++) {
                float4 v = *(const float4*)&sm[SFI(r, cb + i * 4)];
                float p0 = exp2f_fast(fmaf(v.x, LOG2E, -msl));
                float p1 = exp2f_fast(fmaf(v.y, LOG2E, -msl));
                float p2 = exp2f_fast(fmaf(v.z, LOG2E, -msl));
                float p3 = exp2f_fast(fmaf(v.w, LOG2E, -msl));
                sum += p0 + p1 + p2 + p3;
                __half2 h01 = {__float2half_rn(p0), __float2half_rn(p1)};
                __half2 h23 = {__float2half_rn(p2), __float2half_rn(p3)};
                const int c = cb + i * 4;
                uint32_t off = PB + SWZPG(r, c >> 3) + (uint32_t)((c & 7) * 2);
                uint2 pk;
                pk.x = *(uint32_t*)&h01;
                pk.y = *(uint32_t*)&h23;
                *(uint2*)(smb + off) = pk;
            }
            sum += __shfl_xor_sync(0xffffffffu, sum, 1);
            if ((tid & 1) == 0) {
                const float scl = exp2f_fast((mold - mnew) * LOG2E);
                sm[MRF + r] = mnew;
                sm[SRF + r] = scl;
                sm[LRF + r] = sm[LRF + r] * scl + sum;
            }
        }
        __syncthreads();

#pragma unroll
        for (int mt = 0; mt < 2; mt++) {
            const int rl = wR * 32 + mt * 16 + (lane >> 2);
            const float s0 = sm[SRF + rl], s1 = sm[SRF + rl + 8];
#pragma unroll
            for (int nt = 0; nt < 8; nt++) {
                oacc[mt][nt][0] *= s0; oacc[mt][nt][1] *= s0;
                oacc[mt][nt][2] *= s1; oacc[mt][nt][3] *= s1;
            }
        }
#pragma unroll
        for (int ks = 0; ks < 4; ks++) {
            uint32_t ap[2][4], bv[8][2];
#pragma unroll
            for (int mt = 0; mt < 2; mt++)
                ldm_x4(ap[mt], sbase + PB + SWZPG(wR * 32 + mt * 16 + aRow, ks * 2 + aG));
            const int vRow = ks * 16 + (lq & 1) * 8 + lr;
#pragma unroll
            for (int np = 0; np < 4; np++) {
                const int gN = ((wC * 64 + np * 16) >> 3) + (lq >> 1);
                uint32_t t4[4];
                ldm_x4t(t4, Vst + SWZH(vRow, gN));
                bv[np*2][0] = t4[0]; bv[np*2][1] = t4[1];
                bv[np*2+1][0] = t4[2]; bv[np*2+1][1] = t4[3];
            }
#pragma unroll
            for (int mt = 0; mt < 2; mt++)
#pragma unroll
                for (int nt = 0; nt < 8; nt++)
                    mma16(oacc[mt][nt], ap[mt], bv[nt]);
        }
    }

    // epilogue: normalize, write ctx fp16
#pragma unroll
    for (int mt = 0; mt < 2; mt++) {
        const int rl = wR * 32 + mt * 16 + (lane >> 2);
        const float i0 = 1.f / sm[LRF + rl], i1 = 1.f / sm[LRF + rl + 8];
        const size_t r0a = gbase + (size_t)(q0 + rl) * D_;
        const size_t r1a = gbase + (size_t)(q0 + rl + 8) * D_;
#pragma unroll
        for (int nt = 0; nt < 8; nt++) {
            const int dd = wC * 64 + nt * 8 + 2 * (lane & 3);
            __half2 hp0 = {__float2half_rn(oacc[mt][nt][0] * i0),
                           __float2half_rn(oacc[mt][nt][1] * i0)};
            __half2 hp1 = {__float2half_rn(oacc[mt][nt][2] * i1),
                           __float2half_rn(oacc[mt][nt][3] * i1)};
            *(__half2*)&g_ch[r0a + dd] = hp0;
            *(__half2*)&g_ch[r1a + dd] = hp1;
        }
    }
}

// ===================== launcher =====================
extern "C" void kernel_launch(void* const* d_in, const int* in_sizes, int n_in,
                              void* d_out, int out_size)
{
    const float* x  = (const float*)d_in[0];
    const float* Wq = (const float*)d_in[1];
    const float* bq = (const float*)d_in[2];
    const float* Wk = (const float*)d_in[3];
    const float* bk = (const float*)d_in[4];
    const float* Wv = (const float*)d_in[5];
    const float* bv = (const float*)d_in[6];
    const float* Wo = (const float*)d_in[7];
    const float* bo = (const float*)d_in[8];
    float* out = (float*)d_out;

    cudaFuncSetAttribute(gemm_qkv,
                         cudaFuncAttributeMaxDynamicSharedMemorySize, GB_SMEM);
    cudaFuncSetAttribute(gemm_out,
                         cudaFuncAttributeMaxDynamicSharedMemorySize, GB_SMEM);
    cudaFuncSetAttribute(attn_tc,
                         cudaFuncAttributeMaxDynamicSharedMemorySize, ATTN_SMEM);

    const int nTot = N4X + 4 * N4W;
    split_all<<<(nTot + 255) / 256, 256>>>(x, Wq, Wk, Wv, Wo);

    const float qscale = 0.08838834764831845f;    // 1/sqrt(HD)
    const dim3 gq(D_ / 128, M_ / 128, 3);
    gemm_qkv<<<gq, 256, GB_SMEM>>>(bq, bk, bv, qscale);

    const dim3 ga(S_ / 128, H_, B_);              // (16, 16, 2)
    attn_tc<<<ga, 256, ATTN_SMEM>>>();

    const dim3 gg(D_ / 128, M_ / 128);
    gemm_out<<<gg, 256, GB_SMEM>>>(bo, out);
}

// round 16
// speedup vs baseline: 1.2482x; 1.2482x over previous
#include <cuda_runtime.h>
#include <cuda_fp16.h>
#include <cstdint>
#include <math.h>

#define B_  2
#define S_  2048
#define D_  2048
#define H_  16
#define HD_ 128
#define M_  (B_ * S_)
#define BS_D (B_ * S_ * D_)
#define WSZ (D_ * D_)
#define LOG2E 1.4426950408889634f

// Scratch (device globals — no allocation allowed)
__device__ __align__(16) __half g_xh[BS_D];
__device__ __align__(16) __half g_wh[4 * WSZ];
__device__ __align__(16) __half g_q[BS_D], g_k[BS_D], g_v[BS_D];
__device__ __align__(16) __half g_ch[BS_D];

// ===================== helpers =====================
__device__ __forceinline__ void cp16(uint32_t dst, const void* src) {
    asm volatile("cp.async.cg.shared.global [%0], [%1], 16;"
                 :: "r"(dst), "l"(src) : "memory");
}
#define CP_COMMIT() asm volatile("cp.async.commit_group;" ::: "memory")
#define CP_WAIT0()  asm volatile("cp.async.wait_group 0;" ::: "memory")
#define CP_WAIT1()  asm volatile("cp.async.wait_group 1;" ::: "memory")

__device__ __forceinline__ void ldm_x4(uint32_t* r, uint32_t addr) {
    asm volatile("ldmatrix.sync.aligned.m8n8.x4.shared.b16 {%0,%1,%2,%3}, [%4];"
                 : "=r"(r[0]), "=r"(r[1]), "=r"(r[2]), "=r"(r[3]) : "r"(addr));
}
__device__ __forceinline__ void ldm_x4t(uint32_t* r, uint32_t addr) {
    asm volatile("ldmatrix.sync.aligned.m8n8.x4.trans.shared.b16 {%0,%1,%2,%3}, [%4];"
                 : "=r"(r[0]), "=r"(r[1]), "=r"(r[2]), "=r"(r[3]) : "r"(addr));
}

// fp16 m16n8k16, fp32 accumulate
__device__ __forceinline__ void mma16(float* d, const uint32_t* a, const uint32_t* b) {
    asm volatile("mma.sync.aligned.m16n8k16.row.col.f32.f16.f16.f32 "
                 "{%0,%1,%2,%3}, {%4,%5,%6,%7}, {%8,%9}, {%0,%1,%2,%3};"
                 : "+f"(d[0]), "+f"(d[1]), "+f"(d[2]), "+f"(d[3])
                 : "r"(a[0]), "r"(a[1]), "r"(a[2]), "r"(a[3]),
                   "r"(b[0]), "r"(b[1]));
}

// fast exp2 on FMA pipe
__device__ __forceinline__ float exp2f_fast(float z) {
    z = fmaxf(z, -126.f);
    float r = z + 12582912.f;
    int   n = __float_as_int(r);
    float f = z - (r - 12582912.f);
    float p = 1.3333558146e-3f;
    p = fmaf(p, f, 9.6180216e-3f);
    p = fmaf(p, f, 5.5504109e-2f);
    p = fmaf(p, f, 2.4022651e-1f);
    p = fmaf(p, f, 6.9314718e-1f);
    p = fmaf(p, f, 1.0f);
    return __int_as_float(__float_as_int(p) + (n << 23));
}

// ===================== fused prepass: fp16 round (x + 4 W) =====================
#define N4X (BS_D / 4)
#define N4W (WSZ / 4)
__global__ __launch_bounds__(256) void split_all(
    const float* __restrict__ x,  const float* __restrict__ Wq,
    const float* __restrict__ Wk, const float* __restrict__ Wv,
    const float* __restrict__ Wo)
{
    int i = blockIdx.x * 256 + threadIdx.x;
    const float* src;
    __half* dst;
    int j;
    if (i < N4X) { src = x; dst = g_xh; j = i; }
    else {
        int w = (i - N4X) / N4W;
        j = (i - N4X) - w * N4W;
        src = (w == 0) ? Wq : (w == 1) ? Wk : (w == 2) ? Wv : Wo;
        dst = g_wh + w * WSZ;
    }
    float4 v = ((const float4*)src)[j];
    __half2 hp0 = {__float2half_rn(v.x), __float2half_rn(v.y)};
    __half2 hp1 = {__float2half_rn(v.z), __float2half_rn(v.w)};
    ((__half2*)dst)[2 * j]     = hp0;
    ((__half2*)dst)[2 * j + 1] = hp1;
}

// ===================== fp16 GEMM: k32 tiles, 2-chunk super-stages, 3 stages =====================
// tile = 128 rows x 32 fp16, R13 conflict-free packing (2 rows per 128B phys row)
#define GB_TILEB   8192
#define GB_CHUNKB  16384                 // A + B for one k32 chunk
#define GB_STAGEB  32768                 // 2 chunks per stage
#define GB_NSTG    3
#define GB_NSC     (D_ / 64)             // 32 super-chunks
#define GB_SMEM    (GB_NSTG * GB_STAGEB + 512)   // 98816 B -> 2 CTAs/SM

__device__ __forceinline__ uint32_t swzoff(int r, int g) {
    return (uint32_t)(((r >> 1) << 7) +
                      (((((r & 1) << 2) | g) ^ ((r >> 1) & 7)) << 4));
}

struct GemmJob { const __half *Ah, *Bh; const float* bias;
                 float* Cf; __half* Ch; float scale; };

// issue one k32 chunk (A+B) at byte offset `cbase` within smem
__device__ __forceinline__ void g_issue32(const GemmJob& jb, int row0, int col0,
                                          int k0, uint32_t cbase, int tid) {
    const int r = tid >> 1, g2 = (tid & 1) * 2;
    cp16(cbase + swzoff(r, g2),     jb.Ah + (size_t)(row0 + r) * D_ + k0 + g2 * 8);
    cp16(cbase + swzoff(r, g2 + 1), jb.Ah + (size_t)(row0 + r) * D_ + k0 + g2 * 8 + 8);
    cp16(cbase + GB_TILEB + swzoff(r, g2),
         jb.Bh + (size_t)(col0 + r) * D_ + k0 + g2 * 8);
    cp16(cbase + GB_TILEB + swzoff(r, g2 + 1),
         jb.Bh + (size_t)(col0 + r) * D_ + k0 + g2 * 8 + 8);
}
// issue a super-chunk (2 consecutive k32 chunks) into stage sc%3
__device__ __forceinline__ void g_issue_sc(const GemmJob& jb, int row0, int col0,
                                           int sc, uint32_t sbase, int tid) {
    const uint32_t st = sbase + (uint32_t)((sc % GB_NSTG) * GB_STAGEB);
    g_issue32(jb, row0, col0, sc * 64,      st,             tid);
    g_issue32(jb, row0, col0, sc * 64 + 32, st + GB_CHUNKB, tid);
}

__device__ __forceinline__ void gemm_body(const GemmJob& jb, int bx, int by)
{
    extern __shared__ uint32_t smw[];
    float* bias_s = (float*)(smw + GB_NSTG * GB_STAGEB / 4);
    const int tid = threadIdx.x, lane = tid & 31, wid = tid >> 5;
    const int row0 = by * 128, col0 = bx * 128;
    const uint32_t sbase = (uint32_t)__cvta_generic_to_shared(smw);
    const int m0w = (wid >> 2) * 64, n0w = (wid & 3) * 32;

    if (tid < 128) bias_s[tid] = jb.bias[col0 + tid];

    float acc[4][4][4];
#pragma unroll
    for (int a = 0; a < 4; a++)
#pragma unroll
        for (int b = 0; b < 4; b++)
#pragma unroll
            for (int c = 0; c < 4; c++) acc[a][b][c] = 0.f;

    g_issue_sc(jb, row0, col0, 0, sbase, tid); CP_COMMIT();
    g_issue_sc(jb, row0, col0, 1, sbase, tid); CP_COMMIT();

    const int lq  = lane >> 3;
    const int lr  = lane & 7;
    const int aRow = (lq & 1) * 8 + lr;
    const int aG   = lq >> 1;
    const int bRow = (lq >> 1) * 8 + lr;
    const int bG   = lq & 1;

    for (int sc = 0; sc < GB_NSC; sc++) {
        CP_WAIT1();
        __syncthreads();
        if (sc + 2 < GB_NSC) g_issue_sc(jb, row0, col0, sc + 2, sbase, tid);
        CP_COMMIT();

        const uint32_t stg = sbase + (uint32_t)((sc % GB_NSTG) * GB_STAGEB);

#pragma unroll
        for (int half = 0; half < 2; half++) {
            const uint32_t sAh = stg + (uint32_t)(half * GB_CHUNKB);
            const uint32_t sBh = sAh + GB_TILEB;
#pragma unroll
            for (int ks = 0; ks < 2; ks++) {
                const int gA = ks * 2 + aG;
                const int gB = ks * 2 + bG;
                uint32_t ah[4][4], bh[4][2];
#pragma unroll
                for (int mt = 0; mt < 4; mt++)
                    ldm_x4(ah[mt], sAh + swzoff(m0w + mt * 16 + aRow, gA));
#pragma unroll
                for (int np = 0; np < 2; np++) {
                    uint32_t t[4];
                    ldm_x4(t, sBh + swzoff(n0w + np * 16 + bRow, gB));
                    bh[np*2][0] = t[0]; bh[np*2][1] = t[1];
                    bh[np*2+1][0] = t[2]; bh[np*2+1][1] = t[3];
                }
#pragma unroll
                for (int mt = 0; mt < 4; mt++)
#pragma unroll
                    for (int nt = 0; nt < 4; nt++)
                        mma16(acc[mt][nt], ah[mt], bh[nt]);
            }
        }
    }

#pragma unroll
    for (int mt = 0; mt < 4; mt++) {
        const int r = row0 + m0w + mt * 16 + (lane >> 2);
#pragma unroll
        for (int nt = 0; nt < 4; nt++) {
            const int cc = n0w + nt * 8 + 2 * (lane & 3);
            float v0 = (acc[mt][nt][0] + bias_s[cc]) * jb.scale;
            float v1 = (acc[mt][nt][1] + bias_s[cc + 1]) * jb.scale;
            float v2 = (acc[mt][nt][2] + bias_s[cc]) * jb.scale;
            float v3 = (acc[mt][nt][3] + bias_s[cc + 1]) * jb.scale;
            if (jb.Ch) {
                __half2 p0 = {__float2half_rn(v0), __float2half_rn(v1)};
                __half2 p1 = {__float2half_rn(v2), __float2half_rn(v3)};
                *(__half2*)&jb.Ch[(size_t)r * D_ + col0 + cc] = p0;
                *(__half2*)&jb.Ch[(size_t)(r + 8) * D_ + col0 + cc] = p1;
            } else {
                *(float2*)&jb.Cf[(size_t)r * D_ + col0 + cc] = make_float2(v0, v1);
                *(float2*)&jb.Cf[(size_t)(r + 8) * D_ + col0 + cc] = make_float2(v2, v3);
            }
        }
    }
}

__global__ __launch_bounds__(256, 2) void gemm_qkv(
    const float* __restrict__ bq, const float* __restrict__ bk,
    const float* __restrict__ bv, float qscale)
{
    GemmJob jb;
    const int z = blockIdx.z;
    jb.Ah = g_xh;
    jb.Bh = g_wh + z * WSZ;
    jb.bias = (z == 0) ? bq : (z == 1) ? bk : bv;
    jb.Cf = nullptr;
    jb.Ch = (z == 0) ? g_q : (z == 1) ? g_k : g_v;
    jb.scale = (z == 0) ? qscale : 1.f;
    gemm_body(jb, blockIdx.x, blockIdx.y);
}

__global__ __launch_bounds__(256, 2) void gemm_out(
    const float* __restrict__ bo, float* __restrict__ out)
{
    GemmJob jb;
    jb.Ah = g_ch;
    jb.Bh = g_wh + 3 * WSZ;
    jb.bias = bo; jb.Cf = out; jb.Ch = nullptr; jb.scale = 1.f;
    gemm_body(jb, blockIdx.x, blockIdx.y);
}

// ===================== fp16 mma flash attention (byte-identical to R13) =====================
#define QB  0
#define KB  32768
#define VB  65536
#define PB  131072
#define MRF 36864
#define LRF 36992
#define SRF 37120
#define ATTN_SMEM 148992

#define SWZH(r, g) ((uint32_t)((r) * 256 + ((((g) ^ ((r) & 7))) << 4)))
#define SWZPG(r, g) ((uint32_t)((r) * 128 + ((((g) ^ ((r) & 7))) << 4)))
#define SFI(r, c) (24576 + (r) * 64 + ((c) ^ (((r) & 7) << 2)))

__global__ __launch_bounds__(256) void attn_tc()
{
    extern __shared__ float sm[];
    const int tid = threadIdx.x, lane = tid & 31, wid = tid >> 5;
    const int wR = wid >> 1, wC = wid & 1;
    const int q0 = ((int)gridDim.x - 1 - (int)blockIdx.x) * 128;
    const int h = blockIdx.y, b = blockIdx.z;
    const uint32_t sbase = (uint32_t)__cvta_generic_to_shared(sm);
    const size_t gbase = (size_t)b * S_ * D_ + (size_t)h * HD_;

    if (tid < 128) { sm[MRF + tid] = -1e30f; sm[LRF + tid] = 0.f; }

#pragma unroll
    for (int j = 0; j < 8; j++) {
        int id = tid + 256 * j, r = id >> 4, g = id & 15;
        cp16(sbase + QB + SWZH(r, g), &g_q[gbase + (size_t)(q0 + r) * D_ + g * 8]);
    }
#pragma unroll
    for (int j = 0; j < 4; j++) {
        int id = tid + 256 * j, r = id >> 4, g = id & 15;
        cp16(sbase + KB + SWZH(r, g), &g_k[gbase + (size_t)r * D_ + g * 8]);
        cp16(sbase + VB + SWZH(r, g), &g_v[gbase + (size_t)r * D_ + g * 8]);
    }
    CP_COMMIT();

    const int lq = lane >> 3, lr = lane & 7;
    const int aRow = (lq & 1) * 8 + lr;
    const int aG   = lq >> 1;
    const int bRow = (lq >> 1) * 8 + lr;
    const int bG   = lq & 1;

    float oacc[2][8][4];
#pragma unroll
    for (int a = 0; a < 2; a++)
#pragma unroll
        for (int c = 0; c < 8; c++)
#pragma unroll
            for (int e = 0; e < 4; e++) oacc[a][c][e] = 0.f;

    const int ntiles = q0 / 64 + 2;
    for (int t = 0; t < ntiles; t++) {
        const int s = t & 1;
        const int kv0 = t * 64;
        CP_WAIT0();
        __syncthreads();
        if (t + 1 < ntiles) {
            const size_t kr = gbase + (size_t)(kv0 + 64) * D_;
            const uint32_t so = (uint32_t)((s ^ 1) * 16384);
#pragma unroll
            for (int j = 0; j < 4; j++) {
                int id = tid + 256 * j, r = id >> 4, g = id & 15;
                cp16(sbase + KB + so + SWZH(r, g), &g_k[kr + (size_t)r * D_ + g * 8]);
                cp16(sbase + VB + so + SWZH(r, g), &g_v[kr + (size_t)r * D_ + g * 8]);
            }
            CP_COMMIT();
        }
        const uint32_t Kst = sbase + KB + (uint32_t)(s * 16384);
        const uint32_t Vst = sbase + VB + (uint32_t)(s * 16384);

        float sacc[2][4][4];
#pragma unroll
        for (int a = 0; a < 2; a++)
#pragma unroll
            for (int c = 0; c < 4; c++)
#pragma unroll
                for (int e = 0; e < 4; e++) sacc[a][c][e] = 0.f;

#pragma unroll
        for (int ks = 0; ks < 8; ks++) {
            uint32_t aq[2][4], bk[4][2];
#pragma unroll
            for (int mt = 0; mt < 2; mt++)
                ldm_x4(aq[mt], sbase + QB + SWZH(wR * 32 + mt * 16 + aRow, ks * 2 + aG));
#pragma unroll
            for (int np = 0; np < 2; np++) {
                uint32_t t4[4];
                ldm_x4(t4, Kst + SWZH(wC * 32 + np * 16 + bRow, ks * 2 + bG));
                bk[np*2][0] = t4[0]; bk[np*2][1] = t4[1];
                bk[np*2+1][0] = t4[2]; bk[np*2+1][1] = t4[3];
            }
#pragma unroll
            for (int mt = 0; mt < 2; mt++)
#pragma unroll
                for (int nt = 0; nt < 4; nt++)
                    mma16(sacc[mt][nt], aq[mt], bk[nt]);
        }

#pragma unroll
        for (int mt = 0; mt < 2; mt++) {
            const int rl = wR * 32 + mt * 16 + (lane >> 2);
#pragma unroll
            for (int nt = 0; nt < 4; nt++) {
                const int cl_ = wC * 32 + nt * 8 + 2 * (lane & 3);
                float e0 = (kv0 + cl_     <= q0 + rl)     ? sacc[mt][nt][0] : -1e30f;
                float e1 = (kv0 + cl_ + 1 <= q0 + rl)     ? sacc[mt][nt][1] : -1e30f;
                float e2 = (kv0 + cl_     <= q0 + rl + 8) ? sacc[mt][nt][2] : -1e30f;
                float e3 = (kv0 + cl_ + 1 <= q0 + rl + 8) ? sacc[mt][nt][3] : -1e30f;
                *(float2*)&sm[SFI(rl, cl_)]     = make_float2(e0, e1);
                *(float2*)&sm[SFI(rl + 8, cl_)] = make_float2(e2, e3);
            }
        }
        __syncthreads();

        {
            const int r = tid >> 1, cb = (tid & 1) * 32;
            float mx = -1e30f;
#pragma unroll
            for (int i = 0; i < 8; i++) {
                float4 v = *(const float4*)&sm[SFI(r, cb + i * 4)];
                mx = fmaxf(mx, fmaxf(fmaxf(v.x, v.y), fmaxf(v.z, v.w)));
            }
            mx = fmaxf(mx, __shfl_xor_sync(0xffffffffu, mx, 1));
            const float mold = sm[MRF + r];
            const float mnew = fmaxf(mold, mx);
            const float msl  = mnew * LOG2E;
            float sum = 0.f;
            char* smb = (char*)sm;
#pragma unroll
            for (int i = 0; i < 8; i++) {
                float4 v = *(const float4*)&sm[SFI(r, cb + i * 4)];
                float p0 = exp2f_fast(fmaf(v.x, LOG2E, -msl));
                float p1 = exp2f_fast(fmaf(v.y, LOG2E, -msl));
                float p2 = exp2f_fast(fmaf(v.z, LOG2E, -msl));
                float p3 = exp2f_fast(fmaf(v.w, LOG2E, -msl));
                sum += p0 + p1 + p2 + p3;
                __half2 h01 = {__float2half_rn(p0), __float2half_rn(p1)};
                __half2 h23 = {__float2half_rn(p2), __float2half_rn(p3)};
                const int c = cb + i * 4;
                uint32_t off = PB + SWZPG(r, c >> 3) + (uint32_t)((c & 7) * 2);
                uint2 pk;
                pk.x = *(uint32_t*)&h01;
                pk.y = *(uint32_t*)&h23;
                *(uint2*)(smb + off) = pk;
            }
            sum += __shfl_xor_sync(0xffffffffu, sum, 1);
            if ((tid & 1) == 0) {
                const float scl = exp2f_fast((mold - mnew) * LOG2E);
                sm[MRF + r] = mnew;
                sm[SRF + r] = scl;
                sm[LRF + r] = sm[LRF + r] * scl + sum;
            }
        }
        __syncthreads();

#pragma unroll
        for (int mt = 0; mt < 2; mt++) {
            const int rl = wR * 32 + mt * 16 + (lane >> 2);
            const float s0 = sm[SRF + rl], s1 = sm[SRF + rl + 8];
#pragma unroll
            for (int nt = 0; nt < 8; nt++) {
                oacc[mt][nt][0] *= s0; oacc[mt][nt][1] *= s0;
                oacc[mt][nt][2] *= s1; oacc[mt][nt][3] *= s1;
            }
        }
#pragma unroll
        for (int ks = 0; ks < 4; ks++) {
            uint32_t ap[2][4], bv[8][2];
#pragma unroll
            for (int mt = 0; mt < 2; mt++)
                ldm_x4(ap[mt], sbase + PB + SWZPG(wR * 32 + mt * 16 + aRow, ks * 2 + aG));
            const int vRow = ks * 16 + (lq & 1) * 8 + lr;
#pragma unroll
            for (int np = 0; np < 4; np++) {
                const int gN = ((wC * 64 + np * 16) >> 3) + (lq >> 1);
                uint32_t t4[4];
                ldm_x4t(t4, Vst + SWZH(vRow, gN));
                bv[np*2][0] = t4[0]; bv[np*2][1] = t4[1];
                bv[np*2+1][0] = t4[2]; bv[np*2+1][1] = t4[3];
            }
#pragma unroll
            for (int mt = 0; mt < 2; mt++)
#pragma unroll
                for (int nt = 0; nt < 8; nt++)
                    mma16(oacc[mt][nt], ap[mt], bv[nt]);
        }
    }

    // epilogue: normalize, write ctx fp16
#pragma unroll
    for (int mt = 0; mt < 2; mt++) {
        const int rl = wR * 32 + mt * 16 + (lane >> 2);
        const float i0 = 1.f / sm[LRF + rl], i1 = 1.f / sm[LRF + rl + 8];
        const size_t r0a = gbase + (size_t)(q0 + rl) * D_;
        const size_t r1a = gbase + (size_t)(q0 + rl + 8) * D_;
#pragma unroll
        for (int nt = 0; nt < 8; nt++) {
            const int dd = wC * 64 + nt * 8 + 2 * (lane & 3);
            __half2 hp0 = {__float2half_rn(oacc[mt][nt][0] * i0),
                           __float2half_rn(oacc[mt][nt][1] * i0)};
            __half2 hp1 = {__float2half_rn(oacc[mt][nt][2] * i1),
                           __float2half_rn(oacc[mt][nt][3] * i1)};
            *(__half2*)&g_ch[r0a + dd] = hp0;
            *(__half2*)&g_ch[r1a + dd] = hp1;
        }
    }
}

// ===================== launcher =====================
extern "C" void kernel_launch(void* const* d_in, const int* in_sizes, int n_in,
                              void* d_out, int out_size)
{
    const float* x  = (const float*)d_in[0];
    const float* Wq = (const float*)d_in[1];
    const float* bq = (const float*)d_in[2];
    const float* Wk = (const float*)d_in[3];
    const float* bk = (const float*)d_in[4];
    const float* Wv = (const float*)d_in[5];
    const float* bv = (const float*)d_in[6];
    const float* Wo = (const float*)d_in[7];
    const float* bo = (const float*)d_in[8];
    float* out = (float*)d_out;

    cudaFuncSetAttribute(gemm_qkv,
                         cudaFuncAttributeMaxDynamicSharedMemorySize, GB_SMEM);
    cudaFuncSetAttribute(gemm_out,
                         cudaFuncAttributeMaxDynamicSharedMemorySize, GB_SMEM);
    cudaFuncSetAttribute(attn_tc,
                         cudaFuncAttributeMaxDynamicSharedMemorySize, ATTN_SMEM);

    const int nTot = N4X + 4 * N4W;
    split_all<<<(nTot + 255) / 256, 256>>>(x, Wq, Wk, Wv, Wo);

    const float qscale = 0.08838834764831845f;    // 1/sqrt(HD)
    const dim3 gq(D_ / 128, M_ / 128, 3);
    gemm_qkv<<<gq, 256, GB_SMEM>>>(bq, bk, bv, qscale);

    const dim3 ga(S_ / 128, H_, B_);              // (16, 16, 2)
    attn_tc<<<ga, 256, ATTN_SMEM>>>();

    const dim3 gg(D_ / 128, M_ / 128);
    gemm_out<<<gg, 256, GB_SMEM>>>(bo, out);
}

// round 17
// speedup vs baseline: 1.5189x; 1.2169x over previous
#include <cuda_runtime.h>
#include <cuda_fp16.h>
#include <cstdint>
#include <math.h>

#define B_  2
#define S_  2048
#define D_  2048
#define H_  16
#define HD_ 128
#define M_  (B_ * S_)
#define BS_D (B_ * S_ * D_)
#define WSZ (D_ * D_)
#define LOG2E 1.4426950408889634f

// Scratch (device globals — no allocation allowed)
__device__ __align__(16) __half g_xh[BS_D];
__device__ __align__(16) __half g_wh[4 * WSZ];
__device__ __align__(16) __half g_q[BS_D], g_k[BS_D], g_v[BS_D];
__device__ __align__(16) __half g_ch[BS_D];

// ===================== helpers =====================
__device__ __forceinline__ void cp16(uint32_t dst, const void* src) {
    asm volatile("cp.async.cg.shared.global [%0], [%1], 16;"
                 :: "r"(dst), "l"(src) : "memory");
}
#define CP_COMMIT() asm volatile("cp.async.commit_group;" ::: "memory")
#define CP_WAIT0()  asm volatile("cp.async.wait_group 0;" ::: "memory")
#define CP_WAIT1()  asm volatile("cp.async.wait_group 1;" ::: "memory")

__device__ __forceinline__ void ldm_x4(uint32_t* r, uint32_t addr) {
    asm volatile("ldmatrix.sync.aligned.m8n8.x4.shared.b16 {%0,%1,%2,%3}, [%4];"
                 : "=r"(r[0]), "=r"(r[1]), "=r"(r[2]), "=r"(r[3]) : "r"(addr));
}
__device__ __forceinline__ void ldm_x4t(uint32_t* r, uint32_t addr) {
    asm volatile("ldmatrix.sync.aligned.m8n8.x4.trans.shared.b16 {%0,%1,%2,%3}, [%4];"
                 : "=r"(r[0]), "=r"(r[1]), "=r"(r[2]), "=r"(r[3]) : "r"(addr));
}

// fp16 m16n8k16, fp32 accumulate
__device__ __forceinline__ void mma16(float* d, const uint32_t* a, const uint32_t* b) {
    asm volatile("mma.sync.aligned.m16n8k16.row.col.f32.f16.f16.f32 "
                 "{%0,%1,%2,%3}, {%4,%5,%6,%7}, {%8,%9}, {%0,%1,%2,%3};"
                 : "+f"(d[0]), "+f"(d[1]), "+f"(d[2]), "+f"(d[3])
                 : "r"(a[0]), "r"(a[1]), "r"(a[2]), "r"(a[3]),
                   "r"(b[0]), "r"(b[1]));
}

// fast exp2 on FMA pipe
__device__ __forceinline__ float exp2f_fast(float z) {
    z = fmaxf(z, -126.f);
    float r = z + 12582912.f;
    int   n = __float_as_int(r);
    float f = z - (r - 12582912.f);
    float p = 1.3333558146e-3f;
    p = fmaf(p, f, 9.6180216e-3f);
    p = fmaf(p, f, 5.5504109e-2f);
    p = fmaf(p, f, 2.4022651e-1f);
    p = fmaf(p, f, 6.9314718e-1f);
    p = fmaf(p, f, 1.0f);
    return __int_as_float(__float_as_int(p) + (n << 23));
}

// ===================== fused prepass: fp16 round (x + 4 W) =====================
#define N4X (BS_D / 4)
#define N4W (WSZ / 4)
__global__ __launch_bounds__(256) void split_all(
    const float* __restrict__ x,  const float* __restrict__ Wq,
    const float* __restrict__ Wk, const float* __restrict__ Wv,
    const float* __restrict__ Wo)
{
    int i = blockIdx.x * 256 + threadIdx.x;
    const float* src;
    __half* dst;
    int j;
    if (i < N4X) { src = x; dst = g_xh; j = i; }
    else {
        int w = (i - N4X) / N4W;
        j = (i - N4X) - w * N4W;
        src = (w == 0) ? Wq : (w == 1) ? Wk : (w == 2) ? Wv : Wo;
        dst = g_wh + w * WSZ;
    }
    float4 v = ((const float4*)src)[j];
    __half2 hp0 = {__float2half_rn(v.x), __float2half_rn(v.y)};
    __half2 hp1 = {__float2half_rn(v.z), __float2half_rn(v.w)};
    ((__half2*)dst)[2 * j]     = hp0;
    ((__half2*)dst)[2 * j + 1] = hp1;
}

// ===================== fp16 GEMM: 128x128 tile, 4 warps (64x64 each) =====================
// k32 chunks, 3-stage cp.async, R13 conflict-free swizzle (2 rows per 128B phys row)
#define GB_TILEB  8192
#define GB_STAGEB 16384
#define GB_NSTG   3
#define GB_NCH    (D_ / 32)
#define GB_SMEM   (GB_NSTG * GB_STAGEB + 512)   // 49664 B -> 2 CTAs/SM

__device__ __forceinline__ uint32_t swzoff(int r, int g) {
    return (uint32_t)(((r >> 1) << 7) +
                      (((((r & 1) << 2) | g) ^ ((r >> 1) & 7)) << 4));
}

struct GemmJob { const __half *Ah, *Bh; const float* bias;
                 float* Cf; __half* Ch; float scale; };

__device__ __forceinline__ void g_issue32(const GemmJob& jb, int row0, int col0,
                                          int ch, uint32_t sbase, int tid) {
    const uint32_t st = sbase + (uint32_t)((ch % GB_NSTG) * GB_STAGEB);
    const int k0 = ch * 32;
#pragma unroll
    for (int j = 0; j < 4; j++) {
        int id = tid + 128 * j;            // 0..511
        int r = id >> 2, g = id & 3;
        cp16(st + swzoff(r, g),            jb.Ah + (size_t)(row0 + r) * D_ + k0 + g * 8);
        cp16(st + GB_TILEB + swzoff(r, g), jb.Bh + (size_t)(col0 + r) * D_ + k0 + g * 8);
    }
}

__device__ __forceinline__ void gemm_body(const GemmJob& jb, int bx, int by)
{
    extern __shared__ uint32_t smw[];
    float* bias_s = (float*)(smw + GB_NSTG * GB_STAGEB / 4);
    const int tid = threadIdx.x, lane = tid & 31, wid = tid >> 5;
    const int row0 = by * 128, col0 = bx * 128;
    const uint32_t sbase = (uint32_t)__cvta_generic_to_shared(smw);
    const int m0w = (wid >> 1) * 64, n0w = (wid & 1) * 64;   // 2x2 warp grid, 64x64 tiles

    bias_s[tid] = jb.bias[col0 + tid];

    float acc[4][8][4];
#pragma unroll
    for (int a = 0; a < 4; a++)
#pragma unroll
        for (int b = 0; b < 8; b++)
#pragma unroll
            for (int c = 0; c < 4; c++) acc[a][b][c] = 0.f;

    g_issue32(jb, row0, col0, 0, sbase, tid); CP_COMMIT();
    g_issue32(jb, row0, col0, 1, sbase, tid); CP_COMMIT();

    const int lq  = lane >> 3;
    const int lr  = lane & 7;
    const int aRow = (lq & 1) * 8 + lr;
    const int aG   = lq >> 1;
    const int bRow = (lq >> 1) * 8 + lr;
    const int bG   = lq & 1;

    for (int ch = 0; ch < GB_NCH; ch++) {
        CP_WAIT1();
        __syncthreads();
        if (ch + 2 < GB_NCH) g_issue32(jb, row0, col0, ch + 2, sbase, tid);
        CP_COMMIT();

        const uint32_t stg = sbase + (uint32_t)((ch % GB_NSTG) * GB_STAGEB);
        const uint32_t sAh = stg;
        const uint32_t sBh = stg + GB_TILEB;

#pragma unroll
        for (int ks = 0; ks < 2; ks++) {
            const int gA = ks * 2 + aG;
            const int gB = ks * 2 + bG;
            uint32_t ah[4][4], bh[8][2];
#pragma unroll
            for (int mt = 0; mt < 4; mt++)
                ldm_x4(ah[mt], sAh + swzoff(m0w + mt * 16 + aRow, gA));
#pragma unroll
            for (int np = 0; np < 4; np++) {
                uint32_t t[4];
                ldm_x4(t, sBh + swzoff(n0w + np * 16 + bRow, gB));
                bh[np*2][0] = t[0]; bh[np*2][1] = t[1];
                bh[np*2+1][0] = t[2]; bh[np*2+1][1] = t[3];
            }
#pragma unroll
            for (int mt = 0; mt < 4; mt++)
#pragma unroll
                for (int nt = 0; nt < 8; nt++)
                    mma16(acc[mt][nt], ah[mt], bh[nt]);
        }
    }

#pragma unroll
    for (int mt = 0; mt < 4; mt++) {
        const int r = row0 + m0w + mt * 16 + (lane >> 2);
#pragma unroll
        for (int nt = 0; nt < 8; nt++) {
            const int cc = n0w + nt * 8 + 2 * (lane & 3);
            float v0 = (acc[mt][nt][0] + bias_s[cc]) * jb.scale;
            float v1 = (acc[mt][nt][1] + bias_s[cc + 1]) * jb.scale;
            float v2 = (acc[mt][nt][2] + bias_s[cc]) * jb.scale;
            float v3 = (acc[mt][nt][3] + bias_s[cc + 1]) * jb.scale;
            if (jb.Ch) {
                __half2 p0 = {__float2half_rn(v0), __float2half_rn(v1)};
                __half2 p1 = {__float2half_rn(v2), __float2half_rn(v3)};
                *(__half2*)&jb.Ch[(size_t)r * D_ + col0 + cc] = p0;
                *(__half2*)&jb.Ch[(size_t)(r + 8) * D_ + col0 + cc] = p1;
            } else {
                *(float2*)&jb.Cf[(size_t)r * D_ + col0 + cc] = make_float2(v0, v1);
                *(float2*)&jb.Cf[(size_t)(r + 8) * D_ + col0 + cc] = make_float2(v2, v3);
            }
        }
    }
}

__global__ __launch_bounds__(128, 2) void gemm_qkv(
    const float* __restrict__ bq, const float* __restrict__ bk,
    const float* __restrict__ bv, float qscale)
{
    GemmJob jb;
    const int z = blockIdx.z;
    jb.Ah = g_xh;
    jb.Bh = g_wh + z * WSZ;
    jb.bias = (z == 0) ? bq : (z == 1) ? bk : bv;
    jb.Cf = nullptr;
    jb.Ch = (z == 0) ? g_q : (z == 1) ? g_k : g_v;
    jb.scale = (z == 0) ? qscale : 1.f;
    gemm_body(jb, blockIdx.x, blockIdx.y);
}

__global__ __launch_bounds__(128, 2) void gemm_out(
    const float* __restrict__ bo, float* __restrict__ out)
{
    GemmJob jb;
    jb.Ah = g_ch;
    jb.Bh = g_wh + 3 * WSZ;
    jb.bias = bo; jb.Cf = out; jb.Ch = nullptr; jb.scale = 1.f;
    gemm_body(jb, blockIdx.x, blockIdx.y);
}

// ===================== fp16 mma flash attention (byte-identical to R13) =====================
#define QB  0
#define KB  32768
#define VB  65536
#define PB  131072
#define MRF 36864
#define LRF 36992
#define SRF 37120
#define ATTN_SMEM 148992

#define SWZH(r, g) ((uint32_t)((r) * 256 + ((((g) ^ ((r) & 7))) << 4)))
#define SWZPG(r, g) ((uint32_t)((r) * 128 + ((((g) ^ ((r) & 7))) << 4)))
#define SFI(r, c) (24576 + (r) * 64 + ((c) ^ (((r) & 7) << 2)))

__global__ __launch_bounds__(256) void attn_tc()
{
    extern __shared__ float sm[];
    const int tid = threadIdx.x, lane = tid & 31, wid = tid >> 5;
    const int wR = wid >> 1, wC = wid & 1;
    const int q0 = ((int)gridDim.x - 1 - (int)blockIdx.x) * 128;
    const int h = blockIdx.y, b = blockIdx.z;
    const uint32_t sbase = (uint32_t)__cvta_generic_to_shared(sm);
    const size_t gbase = (size_t)b * S_ * D_ + (size_t)h * HD_;

    if (tid < 128) { sm[MRF + tid] = -1e30f; sm[LRF + tid] = 0.f; }

#pragma unroll
    for (int j = 0; j < 8; j++) {
        int id = tid + 256 * j, r = id >> 4, g = id & 15;
        cp16(sbase + QB + SWZH(r, g), &g_q[gbase + (size_t)(q0 + r) * D_ + g * 8]);
    }
#pragma unroll
    for (int j = 0; j < 4; j++) {
        int id = tid + 256 * j, r = id >> 4, g = id & 15;
        cp16(sbase + KB + SWZH(r, g), &g_k[gbase + (size_t)r * D_ + g * 8]);
        cp16(sbase + VB + SWZH(r, g), &g_v[gbase + (size_t)r * D_ + g * 8]);
    }
    CP_COMMIT();

    const int lq = lane >> 3, lr = lane & 7;
    const int aRow = (lq & 1) * 8 + lr;
    const int aG   = lq >> 1;
    const int bRow = (lq >> 1) * 8 + lr;
    const int bG   = lq & 1;

    float oacc[2][8][4];
#pragma unroll
    for (int a = 0; a < 2; a++)
#pragma unroll
        for (int c = 0; c < 8; c++)
#pragma unroll
            for (int e = 0; e < 4; e++) oacc[a][c][e] = 0.f;

    const int ntiles = q0 / 64 + 2;
    for (int t = 0; t < ntiles; t++) {
        const int s = t & 1;
        const int kv0 = t * 64;
        CP_WAIT0();
        __syncthreads();
        if (t + 1 < ntiles) {
            const size_t kr = gbase + (size_t)(kv0 + 64) * D_;
            const uint32_t so = (uint32_t)((s ^ 1) * 16384);
#pragma unroll
            for (int j = 0; j < 4; j++) {
                int id = tid + 256 * j, r = id >> 4, g = id & 15;
                cp16(sbase + KB + so + SWZH(r, g), &g_k[kr + (size_t)r * D_ + g * 8]);
                cp16(sbase + VB + so + SWZH(r, g), &g_v[kr + (size_t)r * D_ + g * 8]);
            }
            CP_COMMIT();
        }
        const uint32_t Kst = sbase + KB + (uint32_t)(s * 16384);
        const uint32_t Vst = sbase + VB + (uint32_t)(s * 16384);

        float sacc[2][4][4];
#pragma unroll
        for (int a = 0; a < 2; a++)
#pragma unroll
            for (int c = 0; c < 4; c++)
#pragma unroll
                for (int e = 0; e < 4; e++) sacc[a][c][e] = 0.f;

#pragma unroll
        for (int ks = 0; ks < 8; ks++) {
            uint32_t aq[2][4], bk[4][2];
#pragma unroll
            for (int mt = 0; mt < 2; mt++)
                ldm_x4(aq[mt], sbase + QB + SWZH(wR * 32 + mt * 16 + aRow, ks * 2 + aG));
#pragma unroll
            for (int np = 0; np < 2; np++) {
                uint32_t t4[4];
                ldm_x4(t4, Kst + SWZH(wC * 32 + np * 16 + bRow, ks * 2 + bG));
                bk[np*2][0] = t4[0]; bk[np*2][1] = t4[1];
                bk[np*2+1][0] = t4[2]; bk[np*2+1][1] = t4[3];
            }
#pragma unroll
            for (int mt = 0; mt < 2; mt++)
#pragma unroll
                for (int nt = 0; nt < 4; nt++)
                    mma16(sacc[mt][nt], aq[mt], bk[nt]);
        }

#pragma unroll
        for (int mt = 0; mt < 2; mt++) {
            const int rl = wR * 32 + mt * 16 + (lane >> 2);
#pragma unroll
            for (int nt = 0; nt < 4; nt++) {
                const int cl_ = wC * 32 + nt * 8 + 2 * (lane & 3);
                float e0 = (kv0 + cl_     <= q0 + rl)     ? sacc[mt][nt][0] : -1e30f;
                float e1 = (kv0 + cl_ + 1 <= q0 + rl)     ? sacc[mt][nt][1] : -1e30f;
                float e2 = (kv0 + cl_     <= q0 + rl + 8) ? sacc[mt][nt][2] : -1e30f;
                float e3 = (kv0 + cl_ + 1 <= q0 + rl + 8) ? sacc[mt][nt][3] : -1e30f;
                *(float2*)&sm[SFI(rl, cl_)]     = make_float2(e0, e1);
                *(float2*)&sm[SFI(rl + 8, cl_)] = make_float2(e2, e3);
            }
        }
        __syncthreads();

        {
            const int r = tid >> 1, cb = (tid & 1) * 32;
            float mx = -1e30f;
#pragma unroll
            for (int i = 0; i < 8; i++) {
                float4 v = *(const float4*)&sm[SFI(r, cb + i * 4)];
                mx = fmaxf(mx, fmaxf(fmaxf(v.x, v.y), fmaxf(v.z, v.w)));
            }
            mx = fmaxf(mx, __shfl_xor_sync(0xffffffffu, mx, 1));
            const float mold = sm[MRF + r];
            const float mnew = fmaxf(mold, mx);
            const float msl  = mnew * LOG2E;
            float sum = 0.f;
            char* smb = (char*)sm;
#pragma unroll
            for (int i = 0; i < 8; i++) {
                float4 v = *(const float4*)&sm[SFI(r, cb + i * 4)];
                float p0 = exp2f_fast(fmaf(v.x, LOG2E, -msl));
                float p1 = exp2f_fast(fmaf(v.y, LOG2E, -msl));
                float p2 = exp2f_fast(fmaf(v.z, LOG2E, -msl));
                float p3 = exp2f_fast(fmaf(v.w, LOG2E, -msl));
                sum += p0 + p1 + p2 + p3;
                __half2 h01 = {__float2half_rn(p0), __float2half_rn(p1)};
                __half2 h23 = {__float2half_rn(p2), __float2half_rn(p3)};
                const int c = cb + i * 4;
                uint32_t off = PB + SWZPG(r, c >> 3) + (uint32_t)((c & 7) * 2);
                uint2 pk;
                pk.x = *(uint32_t*)&h01;
                pk.y = *(uint32_t*)&h23;
                *(uint2*)(smb + off) = pk;
            }
            sum += __shfl_xor_sync(0xffffffffu, sum, 1);
            if ((tid & 1) == 0) {
                const float scl = exp2f_fast((mold - mnew) * LOG2E);
                sm[MRF + r] = mnew;
                sm[SRF + r] = scl;
                sm[LRF + r] = sm[LRF + r] * scl + sum;
            }
        }
        __syncthreads();

#pragma unroll
        for (int mt = 0; mt < 2; mt++) {
            const int rl = wR * 32 + mt * 16 + (lane >> 2);
            const float s0 = sm[SRF + rl], s1 = sm[SRF + rl + 8];
#pragma unroll
            for (int nt = 0; nt < 8; nt++) {
                oacc[mt][nt][0] *= s0; oacc[mt][nt][1] *= s0;
                oacc[mt][nt][2] *= s1; oacc[mt][nt][3] *= s1;
            }
        }
#pragma unroll
        for (int ks = 0; ks < 4; ks++) {
            uint32_t ap[2][4], bv[8][2];
#pragma unroll
            for (int mt = 0; mt < 2; mt++)
                ldm_x4(ap[mt], sbase + PB + SWZPG(wR * 32 + mt * 16 + aRow, ks * 2 + aG));
            const int vRow = ks * 16 + (lq & 1) * 8 + lr;
#pragma unroll
            for (int np = 0; np < 4; np++) {
                const int gN = ((wC * 64 + np * 16) >> 3) + (lq >> 1);
                uint32_t t4[4];
                ldm_x4t(t4, Vst + SWZH(vRow, gN));
                bv[np*2][0] = t4[0]; bv[np*2][1] = t4[1];
                bv[np*2+1][0] = t4[2]; bv[np*2+1][1] = t4[3];
            }
#pragma unroll
            for (int mt = 0; mt < 2; mt++)
#pragma unroll
                for (int nt = 0; nt < 8; nt++)
                    mma16(oacc[mt][nt], ap[mt], bv[nt]);
        }
    }

    // epilogue: normalize, write ctx fp16
#pragma unroll
    for (int mt = 0; mt < 2; mt++) {
        const int rl = wR * 32 + mt * 16 + (lane >> 2);
        const float i0 = 1.f / sm[LRF + rl], i1 = 1.f / sm[LRF + rl + 8];
        const size_t r0a = gbase + (size_t)(q0 + rl) * D_;
        const size_t r1a = gbase + (size_t)(q0 + rl + 8) * D_;
#pragma unroll
        for (int nt = 0; nt < 8; nt++) {
            const int dd = wC * 64 + nt * 8 + 2 * (lane & 3);
            __half2 hp0 = {__float2half_rn(oacc[mt][nt][0] * i0),
                           __float2half_rn(oacc[mt][nt][1] * i0)};
            __half2 hp1 = {__float2half_rn(oacc[mt][nt][2] * i1),
                           __float2half_rn(oacc[mt][nt][3] * i1)};
            *(__half2*)&g_ch[r0a + dd] = hp0;
            *(__half2*)&g_ch[r1a + dd] = hp1;
        }
    }
}

// ===================== launcher =====================
extern "C" void kernel_launch(void* const* d_in, const int* in_sizes, int n_in,
                              void* d_out, int out_size)
{
    const float* x  = (const float*)d_in[0];
    const float* Wq = (const float*)d_in[1];
    const float* bq = (const float*)d_in[2];
    const float* Wk = (const float*)d_in[3];
    const float* bk = (const float*)d_in[4];
    const float* Wv = (const float*)d_in[5];
    const float* bv = (const float*)d_in[6];
    const float* Wo = (const float*)d_in[7];
    const float* bo = (const float*)d_in[8];
    float* out = (float*)d_out;

    cudaFuncSetAttribute(gemm_qkv,
                         cudaFuncAttributeMaxDynamicSharedMemorySize, GB_SMEM);
    cudaFuncSetAttribute(gemm_out,
                         cudaFuncAttributeMaxDynamicSharedMemorySize, GB_SMEM);
    cudaFuncSetAttribute(attn_tc,
                         cudaFuncAttributeMaxDynamicSharedMemorySize, ATTN_SMEM);

    const int nTot = N4X + 4 * N4W;
    split_all<<<(nTot + 255) / 256, 256>>>(x, Wq, Wk, Wv, Wo);

    const float qscale = 0.08838834764831845f;    // 1/sqrt(HD)
    const dim3 gq(D_ / 128, M_ / 128, 3);
    gemm_qkv<<<gq, 128, GB_SMEM>>>(bq, bk, bv, qscale);

    const dim3 ga(S_ / 128, H_, B_);              // (16, 16, 2)
    attn_tc<<<ga, 256, ATTN_SMEM>>>();

    const dim3 gg(D_ / 128, M_ / 128);
    gemm_out<<<gg, 128, GB_SMEM>>>(bo, out);
}